// round 6
// baseline (speedup 1.0000x reference)
#include <cuda_runtime.h>
#include <cstdint>

// LatticeSnake: B=32, L=512, W=9. Output [B, L, 9,9,9, 1] fp32 (48 MB).
// Doubled walk coords (the 2(L-1) grid offset cancels):
//   residue j:   p = 2*idx[j],         v = acids[j]*mask[j]
//   midpoint k:  p = idx[k]+idx[k+1],  v = (acids[k]+acids[k+1]+1)*mask[k+1]
//   window i:    rel = p - 2*idx[i]+4, hit iff all rel in [0,8]
//
// R6 = R5 with the shared-memory vector-cast alignment bug fixed
// (alignas(16) on all vector-cast smem arrays).
//   stage:   coords + acids + mask -> smem (vectorized)
//   phase A: ballot-compact group-bbox survivors into PACKED int2 list
//            (bbox-relative coords in 3 bytes + value) -- 8 B/survivor
//   fill:    zero own 45.6 KB output slice (after phase A, so fill store
//            wavefronts don't queue ahead of phase-A loads in L1tex)
//   phase B: thread t owns window (t&15), center offsets in registers;
//            per pair: broadcast LDS.64 + 3 usub + 2 max + setp;
//            hits -> RED.ADD.F32 (CTA-private slice, barrier-ordered)

#define LS_L   512
#define LS_W   9
#define LS_W3  729
#define LS_R   16               // windows per CTA
#define LS_NT  256
#define LS_NG  (LS_L / LS_R)    // 32 groups per batch
#define LS_M   (2 * LS_L - 1)   // 1023 snake points

__global__ __launch_bounds__(LS_NT)
void lattice_snake_kernel(const float* __restrict__ acids,
                          const float* __restrict__ mask,
                          const int*   __restrict__ idx,
                          float*       __restrict__ out)
{
    __shared__ alignas(16) int2  surv[LS_M + 1];   // packed survivors (8 B)
    __shared__ alignas(16) int   sidx[LS_L * 3];   // batch coords
    __shared__ alignas(16) float sA[LS_L];
    __shared__ alignas(16) float sM[LS_L];
    __shared__ int sCount;

    const int b    = blockIdx.x >> 5;            // / LS_NG
    const int g    = blockIdx.x & (LS_NG - 1);
    const int i0   = g * LS_R;
    const int tid  = threadIdx.x;
    const int lane = tid & 31;

    const int*   gi = idx   + (size_t)b * LS_L * 3;
    const float* ga = acids + (size_t)b * LS_L;
    const float* gm = mask  + (size_t)b * LS_L;
    float* gout = out + (size_t)(b * LS_L + i0) * LS_W3;

    // ---- stage inputs (coalesced vector loads) ----
    {
        const int4* gi4 = reinterpret_cast<const int4*>(gi);
        int4* s4 = reinterpret_cast<int4*>(sidx);
        #pragma unroll
        for (int e = tid; e < (LS_L * 3) / 4; e += LS_NT) s4[e] = gi4[e];
        const float4* ga4 = reinterpret_cast<const float4*>(ga);
        const float4* gm4 = reinterpret_cast<const float4*>(gm);
        float4* a4 = reinterpret_cast<float4*>(sA);
        float4* m4 = reinterpret_cast<float4*>(sM);
        for (int e = tid; e < LS_L / 4; e += LS_NT) { a4[e] = ga4[e]; m4[e] = gm4[e]; }
    }
    if (tid == 0) sCount = 0;
    __syncthreads();

    // ---- group bbox over the 16 window centers (doubled coords) ----
    int xmin =  0x7fffffff, ymin =  0x7fffffff, zmin =  0x7fffffff;
    int xmax = -0x7fffffff, ymax = -0x7fffffff, zmax = -0x7fffffff;
    #pragma unroll
    for (int r = 0; r < LS_R; r++) {
        const int jj = 3 * (i0 + r);
        const int x = 2 * sidx[jj + 0];
        const int y = 2 * sidx[jj + 1];
        const int z = 2 * sidx[jj + 2];
        xmin = min(xmin, x); xmax = max(xmax, x);
        ymin = min(ymin, y); ymax = max(ymax, y);
        zmin = min(zmin, z); zmax = max(zmax, z);
    }
    const int gxl = xmin - 4, gxh = xmax + 4;
    const int gyl = ymin - 4, gyh = ymax + 4;
    const int gzl = zmin - 4, gzh = zmax + 4;

    // this thread's window-center offsets for phase B (window = tid & 15)
    const int wl = tid & 15;
    const int cj = 3 * (i0 + wl);
    const unsigned cox = (unsigned)(2 * sidx[cj + 0] - xmin);   // in [0,~60]
    const unsigned coy = (unsigned)(2 * sidx[cj + 1] - ymin);
    const unsigned coz = (unsigned)(2 * sidx[cj + 2] - zmin);

    // ---- phase A: scan 1023 points, ballot-compact packed survivors ----
    for (int j0 = 0; j0 < LS_M; j0 += LS_NT) {
        const int j = j0 + tid;
        int px = 0, py = 0, pz = 0;
        float v = 0.f;
        bool hit = false;
        if (j < LS_M) {
            const bool isRes = (j < LS_L);
            const int k  = isRes ? j : j - LS_L;
            const int jj = 3 * k;
            if (isRes) {
                px = 2 * sidx[jj + 0];
                py = 2 * sidx[jj + 1];
                pz = 2 * sidx[jj + 2];
                v  = sA[k] * sM[k];
            } else {
                px = sidx[jj + 0] + sidx[jj + 3];
                py = sidx[jj + 1] + sidx[jj + 4];
                pz = sidx[jj + 2] + sidx[jj + 5];
                v  = (sA[k] + sA[k + 1] + 1.0f) * sM[k + 1];
            }
            hit = (px >= gxl) & (px <= gxh) &
                  (py >= gyl) & (py <= gyh) &
                  (pz >= gzl) & (pz <= gzh);
        }
        const unsigned m = __ballot_sync(0xffffffffu, hit);
        if (m == 0) continue;
        const int leader = __ffs(m) - 1;
        int base = 0;
        if (lane == leader) base = atomicAdd(&sCount, __popc(m));
        base = __shfl_sync(0xffffffffu, base, leader);
        if (hit) {
            const int pos = base + __popc(m & ((1u << lane) - 1u));
            // bbox-relative coords, each fits in 8 bits
            const unsigned packed = (unsigned)(px - gxl)
                                  | ((unsigned)(py - gyl) << 8)
                                  | ((unsigned)(pz - gzl) << 16);
            surv[pos] = make_int2((int)packed, __float_as_int(v));
        }
    }

    // ---- fill: zero own slice (16*729 = 2916 float4), after phase A ----
    {
        float4* o4 = reinterpret_cast<float4*>(gout);
        const float4 z = make_float4(0.f, 0.f, 0.f, 0.f);
        #pragma unroll
        for (int e = tid; e < (LS_R * LS_W3) / 4; e += LS_NT) o4[e] = z;
    }
    __syncthreads();   // fill STGs + survivor list ordered before REDs

    // ---- phase B: survivor x window; 16 survivors-rounds per 256 threads
    const int nS = sCount;
    float* gw = gout + wl * LS_W3;
    for (int s = tid >> 4; s < nS; s += LS_NT / LS_R) {
        const int2 pv = surv[s];                  // broadcast LDS.64
        const unsigned pr = (unsigned)pv.x;
        // rel = p - c + 4; bbox origin cancels in the relative forms
        const unsigned rx = (pr & 255u)         - cox;
        const unsigned ry = ((pr >> 8) & 255u)  - coy;
        const unsigned rz = (pr >> 16)          - coz;
        if (max(rx, max(ry, rz)) <= 8u) {
            const int lin = (int)((rx * LS_W + ry) * LS_W + rz);
            atomicAdd(&gw[lin], __int_as_float(pv.y));   // RED.ADD.F32
        }
    }
}

extern "C" void kernel_launch(void* const* d_in, const int* in_sizes, int n_in,
                              void* d_out, int out_size)
{
    const float* acids = (const float*)d_in[0];   // [B, L]
    const float* mask  = (const float*)d_in[1];   // [B, L]
    const int*   idx   = (const int*)  d_in[2];   // [B, L, 3]
    float*       out   = (float*)d_out;           // [B, L, 9,9,9, 1]

    const int nB = in_sizes[0] / LS_L;            // 32
    lattice_snake_kernel<<<nB * LS_NG, LS_NT>>>(acids, mask, idx, out);
}

// round 7
// speedup vs baseline: 1.2224x; 1.2224x over previous
#include <cuda_runtime.h>
#include <cstdint>

// LatticeSnake: B=32, L=512, W=9. Output [B, L, 9,9,9, 1] fp32 (48 MB).
// Doubled walk coords (the 2(L-1) grid offset cancels):
//   residue j:   p = 2*idx[j],         v = acids[j]*mask[j]
//   midpoint k:  p = idx[k]+idx[k+1],  v = (acids[k]+acids[k+1]+1)*mask[k+1]
//   voxel (i,r): value = sum of points at p == 2*idx[i] + r - 4
//
// R7: GATHER via per-CTA dense grid (16 windows/CTA, 1024 CTAs).
//   The union of 16 windows spans a box with per-axis extents
//   (2a+9)(2b+9)(2c+9), a+b+c <= 15  ->  max 19^3 = 6859 cells (27.4 KB).
//   1) stage coords/acids/mask to smem
//   2) zero grid over actual bbox volume
//   3) scan 1023 points once; points inside bbox accumulate into grid
//      (smem atomicAdd; duplicates sum correctly)
//   4) every output voxel = ONE grid LDS + ONE coalesced STG.32.
//   No output atomics, no fill pass, output written exactly once.

#define LS_L    512
#define LS_W    9
#define LS_W3   729
#define LS_R    16               // windows per CTA
#define LS_NT   256
#define LS_NG   (LS_L / LS_R)    // 32 groups per batch
#define LS_M    (2 * LS_L - 1)   // 1023 snake points
#define GRIDPAD 6912             // >= 19^3 = 6859, mult of 4

__global__ __launch_bounds__(LS_NT)
void lattice_snake_kernel(const float* __restrict__ acids,
                          const float* __restrict__ mask,
                          const int*   __restrict__ idx,
                          float*       __restrict__ out)
{
    __shared__ alignas(16) float grid[GRIDPAD];    // 27648 B
    __shared__ alignas(16) int   sidx[LS_L * 3];   //  6144 B
    __shared__ alignas(16) float sA[LS_L];         //  2048 B
    __shared__ alignas(16) float sM[LS_L];         //  2048 B
    __shared__ int sAw[LS_R];                      // per-window grid base

    const int b   = blockIdx.x >> 5;            // / LS_NG
    const int g   = blockIdx.x & (LS_NG - 1);
    const int i0  = g * LS_R;
    const int tid = threadIdx.x;

    const int*   gi = idx   + (size_t)b * LS_L * 3;
    const float* ga = acids + (size_t)b * LS_L;
    const float* gm = mask  + (size_t)b * LS_L;
    float* gout = out + (size_t)(b * LS_L + i0) * LS_W3;

    // ---- stage inputs ----
    {
        const int4* gi4 = reinterpret_cast<const int4*>(gi);
        int4* s4 = reinterpret_cast<int4*>(sidx);
        #pragma unroll
        for (int e = tid; e < (LS_L * 3) / 4; e += LS_NT) s4[e] = gi4[e];
        const float4* ga4 = reinterpret_cast<const float4*>(ga);
        const float4* gm4 = reinterpret_cast<const float4*>(gm);
        float4* a4 = reinterpret_cast<float4*>(sA);
        float4* m4 = reinterpret_cast<float4*>(sM);
        for (int e = tid; e < LS_L / 4; e += LS_NT) { a4[e] = ga4[e]; m4[e] = gm4[e]; }
    }
    __syncthreads();

    // ---- bbox over the 16 window centers (doubled coords) ----
    int xmin =  0x7fffffff, ymin =  0x7fffffff, zmin =  0x7fffffff;
    int xmax = -0x7fffffff, ymax = -0x7fffffff, zmax = -0x7fffffff;
    #pragma unroll
    for (int r = 0; r < LS_R; r++) {
        const int jj = 3 * (i0 + r);
        const int x = 2 * sidx[jj + 0];
        const int y = 2 * sidx[jj + 1];
        const int z = 2 * sidx[jj + 2];
        xmin = min(xmin, x); xmax = max(xmax, x);
        ymin = min(ymin, y); ymax = max(ymax, y);
        zmin = min(zmin, z); zmax = max(zmax, z);
    }
    // grid covers doubled coords [xmin-4 .. xmax+4] etc.
    const int gxl = xmin - 4, gyl = ymin - 4, gzl = zmin - 4;
    const int sx = xmax - xmin + 9;     // <= 19 per axis, sx*sy*sz <= 6859
    const int sy = ymax - ymin + 9;
    const int sz = zmax - zmin + 9;
    const int vol = sx * sy * sz;

    // ---- zero grid over actual volume ----
    {
        float4* g4 = reinterpret_cast<float4*>(grid);
        const float4 z = make_float4(0.f, 0.f, 0.f, 0.f);
        const int n4 = (vol + 3) >> 2;
        for (int e = tid; e < n4; e += LS_NT) g4[e] = z;
    }

    // per-window grid base cell: A = ((2cx-xmin)*sy + (2cy-ymin))*sz + (2cz-zmin)
    if (tid < LS_R) {
        const int jj = 3 * (i0 + tid);
        const int bx = 2 * sidx[jj + 0] - xmin;
        const int by = 2 * sidx[jj + 1] - ymin;
        const int bz = 2 * sidx[jj + 2] - zmin;
        sAw[tid] = (bx * sy + by) * sz + bz;
    }

    // this thread's voxel decompositions: lin = tid, tid+256, tid+512
    int relOff[3];
    #pragma unroll
    for (int k = 0; k < 3; k++) {
        const int lin = tid + k * LS_NT;
        const int rx = lin / 81;
        const int ry = (lin - rx * 81) / 9;
        const int rz = lin - rx * 81 - ry * 9;
        relOff[k] = (rx * sy + ry) * sz + rz;   // valid only if lin < 729
    }
    __syncthreads();   // grid zeroed, sAw ready

    // ---- scan all 1023 snake points; accumulate bbox hits into grid ----
    for (int j = tid; j < LS_M; j += LS_NT) {
        int px, py, pz; float v;
        if (j < LS_L) {
            const int jj = 3 * j;
            px = 2 * sidx[jj + 0];
            py = 2 * sidx[jj + 1];
            pz = 2 * sidx[jj + 2];
            v  = sA[j] * sM[j];
        } else {
            const int k  = j - LS_L;            // 0 .. L-2
            const int jj = 3 * k;
            px = sidx[jj + 0] + sidx[jj + 3];
            py = sidx[jj + 1] + sidx[jj + 4];
            pz = sidx[jj + 2] + sidx[jj + 5];
            v  = (sA[k] + sA[k + 1] + 1.0f) * sM[k + 1];
        }
        const unsigned ux = (unsigned)(px - gxl);
        const unsigned uy = (unsigned)(py - gyl);
        const unsigned uz = (unsigned)(pz - gzl);
        if (ux < (unsigned)sx && uy < (unsigned)sy && uz < (unsigned)sz) {
            atomicAdd(&grid[(ux * sy + uy) * sz + uz], v);
        }
    }
    __syncthreads();   // grid complete

    // ---- gather: each voxel = one LDS + one coalesced STG ----
    const bool k2ok = (tid + 2 * LS_NT) < LS_W3;   // lin2 valid?
    #pragma unroll
    for (int w = 0; w < LS_R; w++) {
        const int Aw = sAw[w];                     // broadcast LDS
        float* gw = gout + w * LS_W3;
        gw[tid]          = grid[Aw + relOff[0]];
        gw[tid + LS_NT]  = grid[Aw + relOff[1]];
        if (k2ok) gw[tid + 2 * LS_NT] = grid[Aw + relOff[2]];
    }
}

extern "C" void kernel_launch(void* const* d_in, const int* in_sizes, int n_in,
                              void* d_out, int out_size)
{
    const float* acids = (const float*)d_in[0];   // [B, L]
    const float* mask  = (const float*)d_in[1];   // [B, L]
    const int*   idx   = (const int*)  d_in[2];   // [B, L, 3]
    float*       out   = (float*)d_out;           // [B, L, 9,9,9, 1]

    const int nB = in_sizes[0] / LS_L;            // 32
    lattice_snake_kernel<<<nB * LS_NG, LS_NT>>>(acids, mask, idx, out);
}